// round 15
// baseline (speedup 1.0000x reference)
#include <cuda_runtime.h>
#include <cuda_fp16.h>
#include <mma.h>
using namespace nvcuda;

#define NN 50000
#define NPAD 50048    // 391 * 128, padded rows for unguarded stores
#define EE 800000
#define ETOT 850000   // EE + NN self loops
#define DIM 128       // 4 heads * 32
#define NEG 0.2f

// ---------------- scratch (device globals; no allocation allowed) ----------------
__device__ uint4 g_xlh[NPAD * 16];   // source transform, fp16 (row = 16 uint4)
__device__ uint4 g_xrh[NPAD * 16];   // destination transform, fp16
__device__ float g_h1[NPAD * DIM];   // layer-1 output, fp32 (GEMM input)
__device__ int   g_count[NN];        // zeroed at start of every call (BSS init / scan self-clear)
__device__ int   g_rowptr[NN + 1];
__device__ int   g_cursor[NN];
__device__ int   g_col[ETOT];        // CSR: SOURCE node id, grouped by dst

// ---------------- CSR build ----------------
// Prefix sum; re-zeroes g_count after reading so the next invocation starts clean.
__global__ void scan_kernel() {
    const int T = 1024;
    const int CH = (NN + T - 1) / T;   // 49
    int t = threadIdx.x;
    int b = t * CH;
    int e = min(b + CH, NN);
    int s = 0;
    for (int i = b; i < e; i++) s += g_count[i];
    __shared__ int sh[T];
    sh[t] = s;
    __syncthreads();
    for (int off = 1; off < T; off <<= 1) {
        int v = (t >= off) ? sh[t - off] : 0;
        __syncthreads();
        sh[t] += v;
        __syncthreads();
    }
    int run = (t == 0) ? 0 : sh[t - 1];
    for (int i = b; i < e; i++) {
        int c = g_count[i];
        g_count[i] = 0;          // self-clear for next invocation
        g_rowptr[i] = run;
        g_cursor[i] = run;
        run += c;
    }
    if (t == 0) g_rowptr[NN] = sh[T - 1];
}

__global__ void scatter_kernel(const int* __restrict__ ei) {
    int e = blockIdx.x * blockDim.x + threadIdx.x;
    if (e >= ETOT) return;
    int src = (e < EE) ? ei[e] : (e - EE);
    int dst = (e < EE) ? ei[EE + e] : (e - EE);
    int p = atomicAdd(&g_cursor[dst], 1);
    g_col[p] = src;
}

// ---------------- Dual GEMM via fp16 tensor cores (HMMA m16n16k16) --------------
// Per block: 128 rows x 256 cols (Wl's 128 ++ Wr's 128), K=128 in 32-chunks.
// 8 warps in a 2x4 grid of 64x64 tiles: wr=w>>2 row block, wc=w&3 col block.
// Square tiles halve fragment smem loads vs 16x256 strips (8 loads / 16 mma).
// Optional fused edge histogram (layer-1 call) overlaps CSR hist with GEMM.
__global__ void __launch_bounds__(256, 1) gemm_half_kernel(
        const float* __restrict__ A, const float* __restrict__ Wl,
        const float* __restrict__ Wr, int M,
        const int* __restrict__ ei, int do_hist) {
    // fused histogram (independent of GEMM work)
    if (do_hist) {
        int stride = gridDim.x * blockDim.x;
        for (int e = blockIdx.x * blockDim.x + threadIdx.x; e < ETOT; e += stride) {
            int dst = (e < EE) ? ei[EE + e] : (e - EE);
            atomicAdd(&g_count[dst], 1);
        }
    }

    __shared__ __align__(16) char sm[34048];
    __half* As = (__half*)sm;                       // 128 x 56 halves (14336 B)
    __half* Ws = (__half*)(sm + 14336);             // 32 x 264 halves (16896 B)
    float (*Cs)[132] = (float(*)[132])sm;           // epilogue reuse (33792 B)

    int tid = threadIdx.x;
    int w = tid >> 5;
    int wr = w >> 2;     // 0..1 : row block of 64
    int wc = w & 3;      // 0..3 : col block of 64
    int m0 = blockIdx.x * 128;

    wmma::fragment<wmma::accumulator, 16, 16, 16, float> acc[4][4];
    #pragma unroll
    for (int i = 0; i < 4; i++)
        #pragma unroll
        for (int j = 0; j < 4; j++) wmma::fill_fragment(acc[i][j], 0.0f);

    for (int k0 = 0; k0 < 128; k0 += 32) {
        // A chunk 128x32 -> fp16 smem (stride 56 halves)
        {
            int r = tid >> 1, c = (tid & 1) * 16;
            float4 f0 = make_float4(0.f,0.f,0.f,0.f), f1 = f0, f2 = f0, f3 = f0;
            if (m0 + r < M) {
                const float* p = &A[(size_t)(m0 + r) * 128 + k0 + c];
                f0 = *(const float4*)p;       f1 = *(const float4*)(p + 4);
                f2 = *(const float4*)(p + 8); f3 = *(const float4*)(p + 12);
            }
            __half2 h0 = __floats2half2_rn(f0.x, f0.y), h1 = __floats2half2_rn(f0.z, f0.w);
            __half2 h2 = __floats2half2_rn(f1.x, f1.y), h3 = __floats2half2_rn(f1.z, f1.w);
            __half2 h4 = __floats2half2_rn(f2.x, f2.y), h5 = __floats2half2_rn(f2.z, f2.w);
            __half2 h6 = __floats2half2_rn(f3.x, f3.y), h7 = __floats2half2_rn(f3.z, f3.w);
            uint4 u0, u1;
            u0.x = *(unsigned*)&h0; u0.y = *(unsigned*)&h1;
            u0.z = *(unsigned*)&h2; u0.w = *(unsigned*)&h3;
            u1.x = *(unsigned*)&h4; u1.y = *(unsigned*)&h5;
            u1.z = *(unsigned*)&h6; u1.w = *(unsigned*)&h7;
            *(uint4*)&As[r * 56 + c]     = u0;
            *(uint4*)&As[r * 56 + c + 8] = u1;
        }
        // W chunk 32 x 256 (Wl cols 0-127, Wr cols 128-255) -> fp16 smem (stride 264)
        {
            int kk = tid >> 3, c = (tid & 7) * 32;
            const float* src = (c < 128) ? Wl : Wr;
            int scol = c & 127;
            const float* p = &src[(size_t)(k0 + kk) * 128 + scol];
            #pragma unroll
            for (int q = 0; q < 4; q++) {
                float4 f0 = *(const float4*)(p + q * 8);
                float4 f1 = *(const float4*)(p + q * 8 + 4);
                __half2 h0 = __floats2half2_rn(f0.x, f0.y);
                __half2 h1 = __floats2half2_rn(f0.z, f0.w);
                __half2 h2 = __floats2half2_rn(f1.x, f1.y);
                __half2 h3 = __floats2half2_rn(f1.z, f1.w);
                uint4 u;
                u.x = *(unsigned*)&h0; u.y = *(unsigned*)&h1;
                u.z = *(unsigned*)&h2; u.w = *(unsigned*)&h3;
                *(uint4*)&Ws[kk * 264 + c + q * 8] = u;
            }
        }
        __syncthreads();
        #pragma unroll
        for (int ks = 0; ks < 32; ks += 16) {
            wmma::fragment<wmma::matrix_a, 16, 16, 16, __half, wmma::row_major> af[4];
            wmma::fragment<wmma::matrix_b, 16, 16, 16, __half, wmma::row_major> bf[4];
            #pragma unroll
            for (int i = 0; i < 4; i++)
                wmma::load_matrix_sync(af[i], &As[(wr * 64 + i * 16) * 56 + ks], 56);
            #pragma unroll
            for (int j = 0; j < 4; j++)
                wmma::load_matrix_sync(bf[j], &Ws[ks * 264 + wc * 64 + j * 16], 264);
            #pragma unroll
            for (int i = 0; i < 4; i++)
                #pragma unroll
                for (int j = 0; j < 4; j++)
                    wmma::mma_sync(acc[i][j], af[i], bf[j], acc[i][j]);
        }
        __syncthreads();
    }

    // Epilogue: 4 waves (row-half rh, col-half hf=xl/xr) through 64x132 fp32 smem.
    #pragma unroll
    for (int rh = 0; rh < 2; rh++) {
        #pragma unroll
        for (int hf = 0; hf < 2; hf++) {
            if (wr == rh && (wc >> 1) == hf) {
                int cbase = (wc & 1) * 64;
                #pragma unroll
                for (int i = 0; i < 4; i++)
                    #pragma unroll
                    for (int j = 0; j < 4; j++)
                        wmma::store_matrix_sync(&Cs[i * 16][cbase + j * 16], acc[i][j],
                                                132, wmma::mem_row_major);
            }
            __syncthreads();
            {
                int r = tid >> 2, cb = (tid & 3) * 4;   // uint4 index within row (16/row)
                uint4* dst = hf ? g_xrh : g_xlh;
                size_t base = (size_t)(m0 + rh * 64 + r) * 16 + cb;
                #pragma unroll
                for (int j = 0; j < 4; j++) {
                    float4 fA = *(const float4*)&Cs[r][(cb + j) * 8];
                    float4 fB = *(const float4*)&Cs[r][(cb + j) * 8 + 4];
                    __half2 h0 = __floats2half2_rn(fA.x, fA.y);
                    __half2 h1 = __floats2half2_rn(fA.z, fA.w);
                    __half2 h2 = __floats2half2_rn(fB.x, fB.y);
                    __half2 h3 = __floats2half2_rn(fB.z, fB.w);
                    uint4 u;
                    u.x = *(unsigned*)&h0; u.y = *(unsigned*)&h1;
                    u.z = *(unsigned*)&h2; u.w = *(unsigned*)&h3;
                    dst[base + j] = u;
                }
            }
            __syncthreads();
        }
    }
}

// ---------------- Fused GAT aggregation: half-warp per edge, depth-4 prefetch ----
// One warp per destination node; each 16-lane half processes one edge per trip.
// Lane owns 8 feature dims (one uint4 of fp16). Softmax without max-shift.
// mode 0: g_h1 = relu(agg + b)          (concat heads, 128-wide fp32)
// mode 1: outp = relu(mean_h(agg) + b)  (32-wide fp32)
__global__ void __launch_bounds__(256) agg_fused_kernel(
        const float* __restrict__ att, const float* __restrict__ bias,
        float* __restrict__ outp, int mode) {
    int d = (blockIdx.x * blockDim.x + threadIdx.x) >> 5;
    int l = threadIdx.x & 31;
    if (d >= NN) return;
    int s0 = g_rowptr[d], s1 = g_rowptr[d + 1];

    int half = l >> 4;
    int hl = l & 15;
    unsigned hmask = 0xFFFFu << (half * 16);

    float4 aA = ((const float4*)att)[2 * hl];
    float4 aB = ((const float4*)att)[2 * hl + 1];
    uint4 qr = g_xrh[(size_t)d * 16 + hl];
    float2 q0 = __half22float2(*(__half2*)&qr.x);
    float2 q1 = __half22float2(*(__half2*)&qr.y);
    float2 q2 = __half22float2(*(__half2*)&qr.z);
    float2 q3 = __half22float2(*(__half2*)&qr.w);

    float den = 0.f;
    float ac0 = 0.f, ac1 = 0.f, ac2 = 0.f, ac3 = 0.f;
    float ac4 = 0.f, ac5 = 0.f, ac6 = 0.f, ac7 = 0.f;

    int i = s0 + half;
    uint4 p0 = make_uint4(0u,0u,0u,0u), p1 = p0, p2 = p0, p3 = p0;
    if (i < s1)     p0 = g_xlh[(size_t)g_col[i] * 16 + hl];
    if (i + 2 < s1) p1 = g_xlh[(size_t)g_col[i + 2] * 16 + hl];
    if (i + 4 < s1) p2 = g_xlh[(size_t)g_col[i + 4] * 16 + hl];
    if (i + 6 < s1) p3 = g_xlh[(size_t)g_col[i + 6] * 16 + hl];

    for (; i < s1; i += 2) {
        uint4 raw = p0;
        p0 = p1; p1 = p2; p2 = p3;
        int nx = i + 8;
        if (nx < s1) p3 = g_xlh[(size_t)g_col[nx] * 16 + hl];

        float2 v0 = __half22float2(*(__half2*)&raw.x);
        float2 v1 = __half22float2(*(__half2*)&raw.y);
        float2 v2 = __half22float2(*(__half2*)&raw.z);
        float2 v3 = __half22float2(*(__half2*)&raw.w);

        float e0 = v0.x + q0.x, e1 = v0.y + q0.y, e2 = v1.x + q1.x, e3 = v1.y + q1.y;
        float e4 = v2.x + q2.x, e5 = v2.y + q2.y, e6 = v3.x + q3.x, e7 = v3.y + q3.y;
        float t =
            ((e0 > 0.f) ? e0 : NEG * e0) * aA.x +
            ((e1 > 0.f) ? e1 : NEG * e1) * aA.y +
            ((e2 > 0.f) ? e2 : NEG * e2) * aA.z +
            ((e3 > 0.f) ? e3 : NEG * e3) * aA.w +
            ((e4 > 0.f) ? e4 : NEG * e4) * aB.x +
            ((e5 > 0.f) ? e5 : NEG * e5) * aB.y +
            ((e6 > 0.f) ? e6 : NEG * e6) * aB.z +
            ((e7 > 0.f) ? e7 : NEG * e7) * aB.w;
        t += __shfl_xor_sync(hmask, t, 1, 4);
        t += __shfl_xor_sync(hmask, t, 2, 4);

        float wgt = __expf(t);
        den += wgt;
        ac0 += wgt * v0.x; ac1 += wgt * v0.y; ac2 += wgt * v1.x; ac3 += wgt * v1.y;
        ac4 += wgt * v2.x; ac5 += wgt * v2.y; ac6 += wgt * v3.x; ac7 += wgt * v3.y;
    }

    // combine halves
    den += __shfl_xor_sync(0xffffffffu, den, 16);
    ac0 += __shfl_xor_sync(0xffffffffu, ac0, 16);
    ac1 += __shfl_xor_sync(0xffffffffu, ac1, 16);
    ac2 += __shfl_xor_sync(0xffffffffu, ac2, 16);
    ac3 += __shfl_xor_sync(0xffffffffu, ac3, 16);
    ac4 += __shfl_xor_sync(0xffffffffu, ac4, 16);
    ac5 += __shfl_xor_sync(0xffffffffu, ac5, 16);
    ac6 += __shfl_xor_sync(0xffffffffu, ac6, 16);
    ac7 += __shfl_xor_sync(0xffffffffu, ac7, 16);

    float invdn = 1.0f / den;
    ac0 *= invdn; ac1 *= invdn; ac2 *= invdn; ac3 *= invdn;
    ac4 *= invdn; ac5 *= invdn; ac6 *= invdn; ac7 *= invdn;

    if (mode == 0) {
        float4 b = ((const float4*)bias)[2 * hl + half];
        float4 o;
        if (half == 0) { o.x = ac0; o.y = ac1; o.z = ac2; o.w = ac3; }
        else           { o.x = ac4; o.y = ac5; o.z = ac6; o.w = ac7; }
        o.x = fmaxf(o.x + b.x, 0.f);
        o.y = fmaxf(o.y + b.y, 0.f);
        o.z = fmaxf(o.z + b.z, 0.f);
        o.w = fmaxf(o.w + b.w, 0.f);
        ((float4*)g_h1)[(size_t)d * 32 + 2 * hl + half] = o;
    } else {
        ac0 += __shfl_xor_sync(0xffffffffu, ac0, 4);
        ac1 += __shfl_xor_sync(0xffffffffu, ac1, 4);
        ac2 += __shfl_xor_sync(0xffffffffu, ac2, 4);
        ac3 += __shfl_xor_sync(0xffffffffu, ac3, 4);
        ac4 += __shfl_xor_sync(0xffffffffu, ac4, 4);
        ac5 += __shfl_xor_sync(0xffffffffu, ac5, 4);
        ac6 += __shfl_xor_sync(0xffffffffu, ac6, 4);
        ac7 += __shfl_xor_sync(0xffffffffu, ac7, 4);
        ac0 += __shfl_xor_sync(0xffffffffu, ac0, 8);
        ac1 += __shfl_xor_sync(0xffffffffu, ac1, 8);
        ac2 += __shfl_xor_sync(0xffffffffu, ac2, 8);
        ac3 += __shfl_xor_sync(0xffffffffu, ac3, 8);
        ac4 += __shfl_xor_sync(0xffffffffu, ac4, 8);
        ac5 += __shfl_xor_sync(0xffffffffu, ac5, 8);
        ac6 += __shfl_xor_sync(0xffffffffu, ac6, 8);
        ac7 += __shfl_xor_sync(0xffffffffu, ac7, 8);
        if (hl < 4) {
            float4 b = ((const float4*)bias)[2 * hl + half];
            float4 o;
            if (half == 0) { o.x = ac0; o.y = ac1; o.z = ac2; o.w = ac3; }
            else           { o.x = ac4; o.y = ac5; o.z = ac6; o.w = ac7; }
            o.x = fmaxf(o.x * 0.25f + b.x, 0.f);
            o.y = fmaxf(o.y * 0.25f + b.y, 0.f);
            o.z = fmaxf(o.z * 0.25f + b.z, 0.f);
            o.w = fmaxf(o.w * 0.25f + b.w, 0.f);
            ((float4*)outp)[(size_t)d * 8 + 2 * hl + half] = o;
        }
    }
}

// ---------------- launch ----------------
// hist fused into gemm1 -> agg1 lands at captured slot 4 for next-round profile.
extern "C" void kernel_launch(void* const* d_in, const int* in_sizes, int n_in,
                              void* d_out, int out_size) {
    const float* x    = (const float*)d_in[0];
    const int*   ei   = (const int*)d_in[1];
    const float* Wl1  = (const float*)d_in[2];
    const float* Wr1  = (const float*)d_in[3];
    const float* att1 = (const float*)d_in[4];
    const float* b1   = (const float*)d_in[5];
    const float* Wl2  = (const float*)d_in[6];
    const float* Wr2  = (const float*)d_in[7];
    const float* att2 = (const float*)d_in[8];
    const float* b2   = (const float*)d_in[9];
    float* out = (float*)d_out;

    float* d_h1; cudaGetSymbolAddress((void**)&d_h1, g_h1);

    int gemm_blocks = NPAD / 128;                  // 391
    int agg_blocks = (NN * 32 + 255) / 256;        // one warp per dst

    gemm_half_kernel<<<gemm_blocks, 256>>>(x, Wl1, Wr1, NN, ei, 1);   // 1 (+hist)
    scan_kernel<<<1, 1024>>>();                                        // 2 (self-clears g_count)
    scatter_kernel<<<(ETOT + 255) / 256, 256>>>(ei);                   // 3
    agg_fused_kernel<<<agg_blocks, 256>>>(att1, b1, nullptr, 0);       // 4 (probed) -> g_h1
    gemm_half_kernel<<<gemm_blocks, 256>>>(d_h1, Wl2, Wr2, NN, ei, 0); // 5
    agg_fused_kernel<<<agg_blocks, 256>>>(att2, b2, out, 1);           // 6 -> d_out
}